// round 9
// baseline (speedup 1.0000x reference)
#include <cuda_runtime.h>

// Problem dims
#define B_TOT   8192
#define D_DIM   1024
#define H_DIM   400
#define N2_DIM  512
#define L_DIM   256
#define E_NUM   16
#define BL_OFF  (B_TOT * L_DIM)      // 2097152
#define MAX_TILES 96                  // sum ceil(c_e/128) <= 64 + 16 = 80

// -------- device scratch (static: no allocations allowed) --------
__device__ int   g_counts[E_NUM];
__device__ int   g_offsets[E_NUM + 1];
__device__ int   g_cursor[E_NUM];
__device__ int   g_sorted[B_TOT];
__device__ int   g_ntiles;
__device__ int   g_tile_e[MAX_TILES];
__device__ int   g_tile_rb[MAX_TILES];
__device__ int   g_is32;
__device__ float g_h1[(size_t)B_TOT * H_DIM];   // 13.1 MB compact hidden acts

// -------- packed f32x2 helpers (full-rate fp32 on sm_103a) --------
__device__ __forceinline__ void fma2(unsigned long long& c,
                                     unsigned long long a,
                                     unsigned long long b) {
    asm("fma.rn.f32x2 %0, %1, %2, %3;" : "=l"(c) : "l"(a), "l"(b), "l"(c));
}
__device__ __forceinline__ unsigned long long dup2(float v) {
    unsigned long long r;
    asm("mov.b64 %0, {%1, %1};" : "=l"(r) : "f"(v));
    return r;
}
__device__ __forceinline__ void unpack2(unsigned long long p, float& lo, float& hi) {
    asm("mov.b64 {%0, %1}, %2;" : "=f"(lo), "=f"(hi) : "l"(p));
}

// angle_idx may land as int64 (reference asks) or int32 (JAX x64-off downcast).
__device__ __forceinline__ int load_e(const void* p, int i) {
    long long v = g_is32 ? (long long)((const int*)p)[i]
                         : ((const long long*)p)[i];
    return ((int)v) & (E_NUM - 1);
}

// -------- setup kernels: counting sort of rows by expert --------
__global__ void k_zero() {
    int i = threadIdx.x;
    if (i < E_NUM) g_counts[i] = 0;
    if (i == 0) g_is32 = 0;
}

// Probe dtype: if int64, all odd 32-bit words of the first 4096 elements are 0.
__global__ void k_detect(const int* p) {
    int i = blockIdx.x * blockDim.x + threadIdx.x;
    if (i < 4096) {
        if (p[2 * i + 1] != 0) atomicOr(&g_is32, 1);
    }
}

__global__ void k_hist(const void* idx) {
    __shared__ int s[E_NUM];
    if (threadIdx.x < E_NUM) s[threadIdx.x] = 0;
    __syncthreads();
    for (int i = blockIdx.x * blockDim.x + threadIdx.x; i < B_TOT;
         i += gridDim.x * blockDim.x) {
        atomicAdd(&s[load_e(idx, i)], 1);
    }
    __syncthreads();
    if (threadIdx.x < E_NUM && s[threadIdx.x])
        atomicAdd(&g_counts[threadIdx.x], s[threadIdx.x]);
}

__global__ void k_scan() {
    if (threadIdx.x == 0) {
        int off = 0, nt = 0;
        for (int e = 0; e < E_NUM; e++) {
            g_offsets[e] = off;
            g_cursor[e]  = off;
            int c = g_counts[e];
            for (int s = 0; s < c; s += 128) {
                if (nt < MAX_TILES) {
                    g_tile_e[nt]  = e;
                    g_tile_rb[nt] = off + s;
                    nt++;
                }
            }
            off += c;
        }
        g_offsets[E_NUM] = off;
        g_ntiles = nt;
    }
}

__global__ void k_scatter(const void* idx) {
    int i = blockIdx.x * blockDim.x + threadIdx.x;
    if (i < B_TOT) {
        int e = load_e(idx, i);
        int pos = atomicAdd(&g_cursor[e], 1);
        g_sorted[pos] = i;
    }
}

// -------- GEMM1: h1 = relu(x[rows] @ W1[e] + b1[e]) --------
// Block tile 128(M) x 64(N), BK=16, 256 threads, double-buffered smem.
__global__ __launch_bounds__(256) void gemm1_kernel(
    const float* __restrict__ x, const float* __restrict__ W1,
    const float* __restrict__ b1)
{
    int t = blockIdx.y;
    if (t >= g_ntiles) return;
    int e = g_tile_e[t];
    int row_base = g_tile_rb[t];
    int rows = g_offsets[e + 1] - row_base;
    if (rows > 128) rows = 128;
    int n0 = blockIdx.x * 64;

    __shared__ float As[2][16][136];   // [k][m], padded
    __shared__ float Bs[2][16][64];    // [k][n]
    __shared__ int   srow[128];

    int tid = threadIdx.x;
    if (tid < 128) {
        int ii = tid < rows ? tid : rows - 1;
        srow[tid] = g_sorted[row_base + ii];
    }
    __syncthreads();

    int am = tid >> 2, ac = tid & 3;    // A loader: row / k-chunk
    int bk = tid >> 4, bn = tid & 15;   // B loader: k-row / n-chunk

    const float* xr0 = x + (size_t)srow[am] * D_DIM + ac * 4;
    const float* xr1 = x + (size_t)srow[am + 64] * D_DIM + ac * 4;
    const float* wbp = W1 + (size_t)e * (D_DIM * H_DIM)
                          + (size_t)bk * H_DIM + n0 + bn * 4;
    bool bvalid = (n0 + bn * 4) < H_DIM;

    float4 pa0 = *(const float4*)xr0;
    float4 pa1 = *(const float4*)xr1;
    float4 pb  = bvalid ? *(const float4*)wbp : make_float4(0.f, 0.f, 0.f, 0.f);

    {
        int kq = ac * 4;
        As[0][kq+0][am]    = pa0.x; As[0][kq+1][am]    = pa0.y;
        As[0][kq+2][am]    = pa0.z; As[0][kq+3][am]    = pa0.w;
        As[0][kq+0][am+64] = pa1.x; As[0][kq+1][am+64] = pa1.y;
        As[0][kq+2][am+64] = pa1.z; As[0][kq+3][am+64] = pa1.w;
        *(float4*)&Bs[0][bk][bn * 4] = pb;
    }
    __syncthreads();

    int ty = tid >> 4, tx = tid & 15;
    unsigned long long acc[4][4];
#pragma unroll
    for (int p = 0; p < 4; p++)
#pragma unroll
        for (int j = 0; j < 4; j++) acc[p][j] = 0ull;

    const int NK = D_DIM / 16;   // 64
    for (int kt = 0; kt < NK; kt++) {
        int buf = kt & 1;
        if (kt + 1 < NK) {
            int ko = (kt + 1) * 16;
            pa0 = *(const float4*)(xr0 + ko);
            pa1 = *(const float4*)(xr1 + ko);
            pb  = bvalid ? *(const float4*)(wbp + (size_t)ko * H_DIM)
                         : make_float4(0.f, 0.f, 0.f, 0.f);
        }
#pragma unroll
        for (int k = 0; k < 16; k++) {
            const ulonglong2* ap = (const ulonglong2*)&As[buf][k][ty * 8];
            ulonglong2 av0 = ap[0], av1 = ap[1];
            float4 bv = *(const float4*)&Bs[buf][k][tx * 4];
            unsigned long long bb0 = dup2(bv.x), bb1 = dup2(bv.y),
                               bb2 = dup2(bv.z), bb3 = dup2(bv.w);
            fma2(acc[0][0], av0.x, bb0); fma2(acc[0][1], av0.x, bb1);
            fma2(acc[0][2], av0.x, bb2); fma2(acc[0][3], av0.x, bb3);
            fma2(acc[1][0], av0.y, bb0); fma2(acc[1][1], av0.y, bb1);
            fma2(acc[1][2], av0.y, bb2); fma2(acc[1][3], av0.y, bb3);
            fma2(acc[2][0], av1.x, bb0); fma2(acc[2][1], av1.x, bb1);
            fma2(acc[2][2], av1.x, bb2); fma2(acc[2][3], av1.x, bb3);
            fma2(acc[3][0], av1.y, bb0); fma2(acc[3][1], av1.y, bb1);
            fma2(acc[3][2], av1.y, bb2); fma2(acc[3][3], av1.y, bb3);
        }
        if (kt + 1 < NK) {
            int wbuf = buf ^ 1, kq = ac * 4;
            As[wbuf][kq+0][am]    = pa0.x; As[wbuf][kq+1][am]    = pa0.y;
            As[wbuf][kq+2][am]    = pa0.z; As[wbuf][kq+3][am]    = pa0.w;
            As[wbuf][kq+0][am+64] = pa1.x; As[wbuf][kq+1][am+64] = pa1.y;
            As[wbuf][kq+2][am+64] = pa1.z; As[wbuf][kq+3][am+64] = pa1.w;
            *(float4*)&Bs[wbuf][bk][bn * 4] = pb;
        }
        __syncthreads();
    }

#pragma unroll
    for (int p = 0; p < 4; p++) {
        int m0 = ty * 8 + p * 2;
#pragma unroll
        for (int j = 0; j < 4; j++) {
            int n = n0 + tx * 4 + j;
            if (n >= H_DIM) continue;
            float lo, hi;
            unpack2(acc[p][j], lo, hi);
            float bias = b1[e * H_DIM + n];
            lo += bias; hi += bias;
            lo = lo > 0.f ? lo : 0.f;
            hi = hi > 0.f ? hi : 0.f;
            if (m0 < rows)     g_h1[(size_t)(row_base + m0) * H_DIM + n] = lo;
            if (m0 + 1 < rows) g_h1[(size_t)(row_base + m0 + 1) * H_DIM + n] = hi;
        }
    }
}

// -------- GEMM2: sel = h1 @ W2[e] + b2[e], scatter mu/logvar --------
__global__ __launch_bounds__(256) void gemm2_kernel(
    const float* __restrict__ W2, const float* __restrict__ b2,
    float* __restrict__ out)
{
    int t = blockIdx.y;
    if (t >= g_ntiles) return;
    int e = g_tile_e[t];
    int row_base = g_tile_rb[t];
    int rows = g_offsets[e + 1] - row_base;
    if (rows > 128) rows = 128;
    int n0 = blockIdx.x * 64;

    __shared__ float As[2][16][136];
    __shared__ float Bs[2][16][64];
    __shared__ int   srow[128];

    int tid = threadIdx.x;
    if (tid < 128) {
        int ii = tid < rows ? tid : rows - 1;
        srow[tid] = g_sorted[row_base + ii];
    }
    __syncthreads();

    int am = tid >> 2, ac = tid & 3;
    int bk = tid >> 4, bn = tid & 15;

    int r0 = row_base + (am      < rows ? am      : rows - 1);
    int r1 = row_base + (am + 64 < rows ? am + 64 : rows - 1);
    const float* ar0 = g_h1 + (size_t)r0 * H_DIM + ac * 4;
    const float* ar1 = g_h1 + (size_t)r1 * H_DIM + ac * 4;
    const float* wbp = W2 + (size_t)e * (H_DIM * N2_DIM)
                          + (size_t)bk * N2_DIM + n0 + bn * 4;

    float4 pa0 = *(const float4*)ar0;
    float4 pa1 = *(const float4*)ar1;
    float4 pb  = *(const float4*)wbp;

    {
        int kq = ac * 4;
        As[0][kq+0][am]    = pa0.x; As[0][kq+1][am]    = pa0.y;
        As[0][kq+2][am]    = pa0.z; As[0][kq+3][am]    = pa0.w;
        As[0][kq+0][am+64] = pa1.x; As[0][kq+1][am+64] = pa1.y;
        As[0][kq+2][am+64] = pa1.z; As[0][kq+3][am+64] = pa1.w;
        *(float4*)&Bs[0][bk][bn * 4] = pb;
    }
    __syncthreads();

    int ty = tid >> 4, tx = tid & 15;
    unsigned long long acc[4][4];
#pragma unroll
    for (int p = 0; p < 4; p++)
#pragma unroll
        for (int j = 0; j < 4; j++) acc[p][j] = 0ull;

    const int NK = H_DIM / 16;   // 25
    for (int kt = 0; kt < NK; kt++) {
        int buf = kt & 1;
        if (kt + 1 < NK) {
            int ko = (kt + 1) * 16;
            pa0 = *(const float4*)(ar0 + ko);
            pa1 = *(const float4*)(ar1 + ko);
            pb  = *(const float4*)(wbp + (size_t)ko * N2_DIM);
        }
#pragma unroll
        for (int k = 0; k < 16; k++) {
            const ulonglong2* ap = (const ulonglong2*)&As[buf][k][ty * 8];
            ulonglong2 av0 = ap[0], av1 = ap[1];
            float4 bv = *(const float4*)&Bs[buf][k][tx * 4];
            unsigned long long bb0 = dup2(bv.x), bb1 = dup2(bv.y),
                               bb2 = dup2(bv.z), bb3 = dup2(bv.w);
            fma2(acc[0][0], av0.x, bb0); fma2(acc[0][1], av0.x, bb1);
            fma2(acc[0][2], av0.x, bb2); fma2(acc[0][3], av0.x, bb3);
            fma2(acc[1][0], av0.y, bb0); fma2(acc[1][1], av0.y, bb1);
            fma2(acc[1][2], av0.y, bb2); fma2(acc[1][3], av0.y, bb3);
            fma2(acc[2][0], av1.x, bb0); fma2(acc[2][1], av1.x, bb1);
            fma2(acc[2][2], av1.x, bb2); fma2(acc[2][3], av1.x, bb3);
            fma2(acc[3][0], av1.y, bb0); fma2(acc[3][1], av1.y, bb1);
            fma2(acc[3][2], av1.y, bb2); fma2(acc[3][3], av1.y, bb3);
        }
        if (kt + 1 < NK) {
            int wbuf = buf ^ 1, kq = ac * 4;
            As[wbuf][kq+0][am]    = pa0.x; As[wbuf][kq+1][am]    = pa0.y;
            As[wbuf][kq+2][am]    = pa0.z; As[wbuf][kq+3][am]    = pa0.w;
            As[wbuf][kq+0][am+64] = pa1.x; As[wbuf][kq+1][am+64] = pa1.y;
            As[wbuf][kq+2][am+64] = pa1.z; As[wbuf][kq+3][am+64] = pa1.w;
            *(float4*)&Bs[wbuf][bk][bn * 4] = pb;
        }
        __syncthreads();
    }

#pragma unroll
    for (int p = 0; p < 4; p++) {
        int m0 = ty * 8 + p * 2;
#pragma unroll
        for (int j = 0; j < 4; j++) {
            int n = n0 + tx * 4 + j;
            float lo, hi;
            unpack2(acc[p][j], lo, hi);
            float bias = b2[e * N2_DIM + n];
            lo += bias; hi += bias;
            if (m0 < rows) {
                int b = srow[m0];
                if (n < L_DIM) out[(size_t)b * L_DIM + n] = lo;
                else           out[BL_OFF + (size_t)b * L_DIM + (n - L_DIM)] = lo;
            }
            if (m0 + 1 < rows) {
                int b = srow[m0 + 1];
                if (n < L_DIM) out[(size_t)b * L_DIM + n] = hi;
                else           out[BL_OFF + (size_t)b * L_DIM + (n - L_DIM)] = hi;
            }
        }
    }
}

// -------- launch --------
extern "C" void kernel_launch(void* const* d_in, const int* in_sizes, int n_in,
                              void* d_out, int out_size) {
    const float* x   = (const float*)d_in[0];
    const void*  idx = d_in[1];
    const float* W1  = (const float*)d_in[2];
    const float* b1  = (const float*)d_in[3];
    const float* W2  = (const float*)d_in[4];
    const float* b2  = (const float*)d_in[5];
    float* out = (float*)d_out;

    (void)in_sizes; (void)n_in; (void)out_size;

    k_zero<<<1, 32>>>();
    k_detect<<<16, 256>>>((const int*)idx);
    k_hist<<<32, 256>>>(idx);
    k_scan<<<1, 32>>>();
    k_scatter<<<32, 256>>>(idx);

    dim3 g1(7, MAX_TILES);   // ceil(400/64) n-tiles x tile table
    gemm1_kernel<<<g1, 256>>>(x, W1, b1);

    dim3 g2(8, MAX_TILES);   // 512/64 n-tiles
    gemm2_kernel<<<g2, 256>>>(W2, b2, out);
}